// round 1
// baseline (speedup 1.0000x reference)
#include <cuda_runtime.h>
#include <cuda_bf16.h>
#include <cstdint>

// Problem constants
#define NB   64
#define TT   1024
#define EE   256
#define HH   128
#define G3   384          // 3*H
#define GALL 768          // both directions
#define MROWS (NB*TT)     // 65536
#define BOTTLE 32

// ---------------- scratch (static device globals; no runtime alloc) ----------
__device__ float g_wcomb[GALL * EE];          // [768][256] combined W_ih
__device__ float g_bcomb[GALL];               // [768] combined b_ih
__device__ float g_gx[(size_t)MROWS * GALL];  // [65536][768] input gate preacts (192 MiB)
__device__ float g_hsf[(size_t)MROWS * HH];   // forward hidden states  [m][u]
__device__ float g_hsb[(size_t)MROWS * HH];   // backward hidden states [m][u]

// ---------------- helpers ----------------------------------------------------
__device__ __forceinline__ float sigm_f(float x) {
    return __fdividef(1.f, 1.f + __expf(-x));
}
__device__ __forceinline__ float tanh_f(float x) {
    // tanh(x) = 2/(1+exp(-2x)) - 1 ; robust at extremes with __expf
    return __fdividef(2.f, 1.f + __expf(-2.f * x)) - 1.f;
}

// ---------------- kernel 0: pack input weights/biases ------------------------
__global__ void pack_weights(const float* __restrict__ w_ih_f,
                             const float* __restrict__ b_ih_f,
                             const float* __restrict__ w_ih_b,
                             const float* __restrict__ b_ih_b) {
    int i = blockIdx.x * blockDim.x + threadIdx.x;   // 0 .. 768*256-1
    if (i < GALL * EE) {
        int g = i / EE;
        g_wcomb[i] = (g < G3) ? w_ih_f[i] : w_ih_b[i - G3 * EE];
    }
    if (i < GALL) {
        g_bcomb[i] = (i < G3) ? b_ih_f[i] : b_ih_b[i - G3];
    }
}

// ---------------- kernel 1: gx GEMM  [65536,256] x [256,768] -----------------
#define BM 128
#define BN 128
#define BK 32
__global__ __launch_bounds__(256) void gemm_gx(const float* __restrict__ X) {
    __shared__ __align__(16) float As[BK][BM + 4];
    __shared__ __align__(16) float Bs[BK][BN + 4];

    const int m0 = blockIdx.x * BM;
    const int n0 = blockIdx.y * BN;
    const int tid = threadIdx.x;
    const int tx = tid & 15;          // 0..15
    const int ty = tid >> 4;          // 0..15

    float acc[8][8];
#pragma unroll
    for (int i = 0; i < 8; i++)
#pragma unroll
        for (int j = 0; j < 8; j++) acc[i][j] = 0.f;

    for (int k0 = 0; k0 < EE; k0 += BK) {
        // load A tile (128x32) as float4, store transposed As[k][m]
#pragma unroll
        for (int l = 0; l < 4; l++) {
            int lin = tid + l * 256;        // 0..1023
            int r = lin >> 3;               // row 0..127
            int c4 = lin & 7;               // float4 col 0..7
            float4 v = reinterpret_cast<const float4*>(
                X + (size_t)(m0 + r) * EE + k0)[c4];
            As[c4 * 4 + 0][r] = v.x;
            As[c4 * 4 + 1][r] = v.y;
            As[c4 * 4 + 2][r] = v.z;
            As[c4 * 4 + 3][r] = v.w;
        }
        // load B tile (128x32 of wcomb) transposed Bs[k][n]
#pragma unroll
        for (int l = 0; l < 4; l++) {
            int lin = tid + l * 256;
            int r = lin >> 3;
            int c4 = lin & 7;
            float4 v = reinterpret_cast<const float4*>(
                g_wcomb + (size_t)(n0 + r) * EE + k0)[c4];
            Bs[c4 * 4 + 0][r] = v.x;
            Bs[c4 * 4 + 1][r] = v.y;
            Bs[c4 * 4 + 2][r] = v.z;
            Bs[c4 * 4 + 3][r] = v.w;
        }
        __syncthreads();

#pragma unroll
        for (int k = 0; k < BK; k++) {
            float4 a0 = *reinterpret_cast<const float4*>(&As[k][ty * 8]);
            float4 a1 = *reinterpret_cast<const float4*>(&As[k][ty * 8 + 4]);
            float4 b0 = *reinterpret_cast<const float4*>(&Bs[k][tx * 8]);
            float4 b1 = *reinterpret_cast<const float4*>(&Bs[k][tx * 8 + 4]);
            float a[8] = {a0.x, a0.y, a0.z, a0.w, a1.x, a1.y, a1.z, a1.w};
            float b[8] = {b0.x, b0.y, b0.z, b0.w, b1.x, b1.y, b1.z, b1.w};
#pragma unroll
            for (int i = 0; i < 8; i++)
#pragma unroll
                for (int j = 0; j < 8; j++) acc[i][j] += a[i] * b[j];
        }
        __syncthreads();
    }

    // epilogue: add bias, store
    float bc[8];
#pragma unroll
    for (int j = 0; j < 8; j++) bc[j] = g_bcomb[n0 + tx * 8 + j];

#pragma unroll
    for (int i = 0; i < 8; i++) {
        int m = m0 + ty * 8 + i;
        float* dst = g_gx + (size_t)m * GALL + n0 + tx * 8;
        float4 o0 = {acc[i][0] + bc[0], acc[i][1] + bc[1],
                     acc[i][2] + bc[2], acc[i][3] + bc[3]};
        float4 o1 = {acc[i][4] + bc[4], acc[i][5] + bc[5],
                     acc[i][6] + bc[6], acc[i][7] + bc[7]};
        *reinterpret_cast<float4*>(dst) = o0;
        *reinterpret_cast<float4*>(dst + 4) = o1;
    }
}

// ---------------- kernel 2: GRU scan (1 CTA per (dir, batch) chain) ----------
// 512 threads: thread = (u in 0..127, jb in 0..3); w_hh held in registers.
__global__ __launch_bounds__(512, 1) void gru_scan(
    const float* __restrict__ Whh_f, const float* __restrict__ bhh_f,
    const float* __restrict__ Whh_b, const float* __restrict__ bhh_b) {
    __shared__ __align__(16) float sh_h[HH];
    __shared__ __align__(16) float sp[4][3][HH];

    const int tid = threadIdx.x;
    const int u = tid & 127;
    const int jb = tid >> 7;          // 0..3, j-range [jb*32, jb*32+32)
    const int blk = blockIdx.x;       // 0..127
    const int n = blk & 63;
    const int dir = blk >> 6;

    const float* Whh = dir ? Whh_b : Whh_f;
    const float* bhh = dir ? bhh_b : bhh_f;
    float* hs_out = dir ? g_hsb : g_hsf;
    const float* gx = g_gx + (size_t)n * TT * GALL + dir * G3;

    // register-resident W_hh slices for this thread's (u, jb)
    float wr[32], wz[32], wn[32];
#pragma unroll
    for (int q = 0; q < 32; q++) {
        int j = jb * 32 + q;
        wr[q] = Whh[(size_t)u * HH + j];
        wz[q] = Whh[(size_t)(HH + u) * HH + j];
        wn[q] = Whh[(size_t)(2 * HH + u) * HH + j];
    }
    float bhr = 0.f, bhz = 0.f, bhn = 0.f, hold = 0.f;
    if (jb == 0) {
        bhr = bhh[u];
        bhz = bhh[HH + u];
        bhn = bhh[2 * HH + u];
        sh_h[u] = 0.f;
    }
    __syncthreads();

    int t = dir ? (TT - 1) : 0;
    const int dt = dir ? -1 : 1;

    for (int s = 0; s < TT; s++, t += dt) {
        // prefetch this step's gx (consumed after the FMA phase -> latency hidden)
        float gxr = 0.f, gxz = 0.f, gxn = 0.f;
        if (jb == 0) {
            const float* gxt = gx + (size_t)t * GALL;
            gxr = __ldcs(gxt + u);
            gxz = __ldcs(gxt + HH + u);
            gxn = __ldcs(gxt + 2 * HH + u);
        }

        // partial matvec over this thread's 32 j's
        float ar = 0.f, az = 0.f, an = 0.f;
        const float4* h4 = reinterpret_cast<const float4*>(sh_h + jb * 32);
#pragma unroll
        for (int q4 = 0; q4 < 8; q4++) {
            float4 hv = h4[q4];
            ar += wr[q4 * 4 + 0] * hv.x; az += wz[q4 * 4 + 0] * hv.x; an += wn[q4 * 4 + 0] * hv.x;
            ar += wr[q4 * 4 + 1] * hv.y; az += wz[q4 * 4 + 1] * hv.y; an += wn[q4 * 4 + 1] * hv.y;
            ar += wr[q4 * 4 + 2] * hv.z; az += wz[q4 * 4 + 2] * hv.z; an += wn[q4 * 4 + 2] * hv.z;
            ar += wr[q4 * 4 + 3] * hv.w; az += wz[q4 * 4 + 3] * hv.w; an += wn[q4 * 4 + 3] * hv.w;
        }
        sp[jb][0][u] = ar;
        sp[jb][1][u] = az;
        sp[jb][2][u] = an;
        __syncthreads();

        if (jb == 0) {
            float ghr = sp[0][0][u] + sp[1][0][u] + sp[2][0][u] + sp[3][0][u] + bhr;
            float ghz = sp[0][1][u] + sp[1][1][u] + sp[2][1][u] + sp[3][1][u] + bhz;
            float ghn = sp[0][2][u] + sp[1][2][u] + sp[2][2][u] + sp[3][2][u] + bhn;
            float r = sigm_f(gxr + ghr);
            float z = sigm_f(gxz + ghz);
            float nn = tanh_f(gxn + r * ghn);
            float hnew = (1.f - z) * nn + z * hold;
            hold = hnew;
            sh_h[u] = hnew;
            hs_out[((size_t)n * TT + t) * HH + u] = hnew;
        }
        __syncthreads();
    }
}

// ---------------- kernel 3: output projection [65536,256] x [256,32] ---------
__global__ __launch_bounds__(256) void proj_kernel(
    const float* __restrict__ wo, const float* __restrict__ bo,
    float* __restrict__ out) {
    __shared__ __align__(16) float ws[EE][BOTTLE];  // ws[c][b] = wo[b][c]
    __shared__ float bs[BOTTLE];

    const int tid = threadIdx.x;
    for (int i = tid; i < EE * BOTTLE; i += 256) {
        int c = i >> 5;
        int b = i & 31;
        ws[c][b] = wo[b * EE + c];
    }
    if (tid < BOTTLE) bs[tid] = bo[tid];
    __syncthreads();

    const int m = blockIdx.x * 256 + tid;   // one row per thread
    float acc[BOTTLE];
#pragma unroll
    for (int b = 0; b < BOTTLE; b++) acc[b] = bs[b];

    const float* rf = g_hsf + (size_t)m * HH;
    const float* rb = g_hsb + (size_t)m * HH;
#pragma unroll 4
    for (int c = 0; c < HH; c++) {
        float v = rf[c];
        const float4* w4 = reinterpret_cast<const float4*>(ws[c]);
#pragma unroll
        for (int b4 = 0; b4 < 8; b4++) {
            float4 wv = w4[b4];
            acc[b4 * 4 + 0] += v * wv.x;
            acc[b4 * 4 + 1] += v * wv.y;
            acc[b4 * 4 + 2] += v * wv.z;
            acc[b4 * 4 + 3] += v * wv.w;
        }
    }
#pragma unroll 4
    for (int c = 0; c < HH; c++) {
        float v = rb[c];
        const float4* w4 = reinterpret_cast<const float4*>(ws[HH + c]);
#pragma unroll
        for (int b4 = 0; b4 < 8; b4++) {
            float4 wv = w4[b4];
            acc[b4 * 4 + 0] += v * wv.x;
            acc[b4 * 4 + 1] += v * wv.y;
            acc[b4 * 4 + 2] += v * wv.z;
            acc[b4 * 4 + 3] += v * wv.w;
        }
    }

    float4* dst = reinterpret_cast<float4*>(out + (size_t)m * BOTTLE);
#pragma unroll
    for (int b4 = 0; b4 < 8; b4++) {
        float4 o = {acc[b4 * 4 + 0], acc[b4 * 4 + 1],
                    acc[b4 * 4 + 2], acc[b4 * 4 + 3]};
        dst[b4] = o;
    }
}

// ---------------- launch ------------------------------------------------------
extern "C" void kernel_launch(void* const* d_in, const int* in_sizes, int n_in,
                              void* d_out, int out_size) {
    const float* x      = (const float*)d_in[0];
    const float* w_ih_f = (const float*)d_in[1];
    const float* w_hh_f = (const float*)d_in[2];
    const float* b_ih_f = (const float*)d_in[3];
    const float* b_hh_f = (const float*)d_in[4];
    const float* w_ih_b = (const float*)d_in[5];
    const float* w_hh_b = (const float*)d_in[6];
    const float* b_ih_b = (const float*)d_in[7];
    const float* b_hh_b = (const float*)d_in[8];
    const float* w_out  = (const float*)d_in[9];
    const float* b_out  = (const float*)d_in[10];
    float* out = (float*)d_out;

    pack_weights<<<GALL, 256>>>(w_ih_f, b_ih_f, w_ih_b, b_ih_b);
    gemm_gx<<<dim3(MROWS / BM, GALL / BN), 256>>>(x);
    gru_scan<<<128, 512>>>(w_hh_f, b_hh_f, w_hh_b, b_hh_b);
    proj_kernel<<<MROWS / 256, 256>>>(w_out, b_out, out);
}